// round 6
// baseline (speedup 1.0000x reference)
#include <cuda_runtime.h>
#include <math.h>

#define B 64
#define NTOK 4096
#define D 64
#define S 8
#define HID 128
#define CHUNKS 8
#define NC (NTOK / CHUNKS)   /* 512 tokens per k_main block */
#define TILE 256
#define TPB 256
#define XSW 34               /* u32 words per token row (32 used + 2 pad) */

typedef unsigned long long u64t;

__device__ __forceinline__ u64t f2_fma(u64t a, u64t b, u64t c) {
    u64t d;
    asm("fma.rn.f32x2 %0, %1, %2, %3;" : "=l"(d) : "l"(a), "l"(b), "l"(c));
    return d;
}
__device__ __forceinline__ u64t f2_add(u64t a, u64t b) {
    u64t d;
    asm("add.rn.f32x2 %0, %1, %2;" : "=l"(d) : "l"(a), "l"(b));
    return d;
}
__device__ __forceinline__ float2 f2_unpack(u64t a) {
    float2 r;
    asm("mov.b64 {%0, %1}, %2;" : "=f"(r.x), "=f"(r.y) : "l"(a));
    return r;
}
__device__ __forceinline__ u64t f2_splat(float a) {
    u64t d;
    asm("mov.b64 %0, {%1, %1};" : "=l"(d) : "f"(a));
    return d;
}
// bf16x2 (u32) -> packed f32x2: lo bf16 -> lane0, hi bf16 -> lane1
__device__ __forceinline__ u64t bfpair(unsigned int a) {
    u64t d;
    asm("{\n\t.reg .b32 lo, hi;\n\tshl.b32 lo, %1, 16;\n\tand.b32 hi, %1, 0xFFFF0000;\n\tmov.b64 %0, {lo, hi};\n\t}"
        : "=l"(d) : "r"(a));
    return d;
}
__device__ __forceinline__ unsigned int bfpack(float lo, float hi) {
    unsigned int r;
    asm("cvt.rn.bf16x2.f32 %0, %1, %2;" : "=r"(r) : "f"(hi), "f"(lo));
    return r;
}

// ---------------- device scratch ----------------
__device__ float g_slots[B * S * D];
__device__ float g_qhat[B * S * D];
__device__ float g_sq[B * S];
__device__ float g_cst[B * S];
__device__ float g_P[B * CHUNKS * S * D];
__device__ float g_Td[B * CHUNKS * 16];
__device__ float g_wqk[D * D];
__device__ float g_bqk[D];
__device__ float g_wqbk[D];
__device__ float g_bqbk[1];
__device__ int g_cnt[B];

// ---------------- precompute folded weight products ----------------
__global__ __launch_bounds__(256) void k_pre(const float* __restrict__ wq,
                                             const float* __restrict__ bq,
                                             const float* __restrict__ wk,
                                             const float* __restrict__ bk) {
    int t = threadIdx.x;
    for (int o = t; o < D * D; o += 256) {
        int e = o >> 6, e2 = o & 63;
        float s = 0.f;
        for (int d = 0; d < D; d++) s += wq[e * D + d] * wk[e2 * D + d];
        g_wqk[o] = s;
    }
    for (int e2 = t; e2 < D; e2 += 256) {
        float s = 0.f;
        for (int d = 0; d < D; d++) s += bq[d] * wk[e2 * D + d];
        g_bqk[e2] = s;
    }
    for (int e = t; e < D; e += 256) {
        float s = 0.f;
        for (int d = 0; d < D; d++) s += wq[e * D + d] * bk[d];
        g_wqbk[e] = s;
    }
    if (t == 0) {
        float s = 0.f;
        for (int d = 0; d < D; d++) s += bq[d] * bk[d];
        g_bqbk[0] = s;
    }
}

// ---------------- q-fold (init path) ----------------
__device__ void compute_q_from_slots(int b, const float* s_slots,
                                     const float* __restrict__ g_sl,
                                     const float* __restrict__ be_sl,
                                     const float* __restrict__ g_in,
                                     const float* __restrict__ be_in,
                                     float* s_sln, float* s_tmp) {
    int tid = threadIdx.x;
    int w = tid >> 5, lane = tid & 31;
    {
        float v0 = s_slots[w * 64 + lane];
        float v1 = s_slots[w * 64 + 32 + lane];
        float s = v0 + v1, s2 = v0 * v0 + v1 * v1;
#pragma unroll
        for (int off = 16; off; off >>= 1) {
            s += __shfl_xor_sync(0xffffffffu, s, off);
            s2 += __shfl_xor_sync(0xffffffffu, s2, off);
        }
        float m = s * (1.f / 64.f);
        float var = s2 * (1.f / 64.f) - m * m;
        float r = rsqrtf(var + 1e-5f);
        s_sln[w * 64 + lane] = (v0 - m) * r * g_sl[lane] + be_sl[lane];
        s_sln[w * 64 + 32 + lane] = (v1 - m) * r * g_sl[lane + 32] + be_sl[lane + 32];
    }
    __syncthreads();
    for (int rep = 0; rep < 2; rep++) {
        int idx = tid + rep * 256;
        int i = idx >> 6, e2 = idx & 63;
        float acc = g_bqk[e2];
#pragma unroll 8
        for (int e = 0; e < 64; e++) acc += s_sln[i * 64 + e] * g_wqk[e * 64 + e2];
        float qt = 0.125f * acc;
        float qh = qt * g_in[e2];
        g_qhat[b * S * D + idx] = qh;
        s_tmp[idx] = qh;
        s_tmp[512 + idx] = qt * be_in[e2];
    }
    __syncthreads();
    if (tid < S) {
        float sq = 0.f, cb = 0.f;
        for (int e2 = 0; e2 < 64; e2++) {
            sq += s_tmp[tid * 64 + e2];
            cb += s_tmp[512 + tid * 64 + e2];
        }
        float qb = g_bqbk[0];
        for (int e = 0; e < 64; e++) qb += s_sln[tid * 64 + e] * g_wqbk[e];
        g_sq[b * S + tid] = sq;
        g_cst[b * S + tid] = cb + 0.125f * qb;
    }
}

// ---------------- init ----------------
__global__ __launch_bounds__(256) void k_init(const float* __restrict__ noise,
                                              const float* __restrict__ mu,
                                              const float* __restrict__ ls,
                                              const float* __restrict__ g_sl,
                                              const float* __restrict__ be_sl,
                                              const float* __restrict__ g_in,
                                              const float* __restrict__ be_in) {
    __shared__ float s_slots[512];
    __shared__ float s_sln[512];
    __shared__ float s_tmp[1024];
    int b = blockIdx.x, tid = threadIdx.x;
    if (tid == 0) g_cnt[b] = 0;
    for (int k = tid; k < 512; k += 256) {
        int d = k & 63;
        float v = mu[d] + expf(ls[d]) * noise[b * 512 + k];
        s_slots[k] = v;
        g_slots[b * 512 + k] = v;
    }
    __syncthreads();
    compute_q_from_slots(b, s_slots, g_sl, be_sl, g_in, be_in, s_sln, s_tmp);
}

// ================= fused main + epilogue =================
// pool layout (floats):
//   main:  [0,8704) xs32 (u32)   [8704,10752) attn_s   [10752,11264) qh
//          [11264,11272) sqs  [11272,11280) csts  [11280,11408) s_red
//   epi:   e_prev 0  e_num 512  e_upd 1024  e_new 1536  e_ff 2048
//          e_h1 2560(1024)  e_gx 3584(1536)  e_gh 5120(1536)
//          e_pp 6656(2048)  e_Td 8704(16)
#define POOL_FLOATS 11408

__global__ __launch_bounds__(TPB, 4) void k_main(
    const float* __restrict__ x,
    const float* __restrict__ wv, const float* __restrict__ bv,
    const float* __restrict__ w_ih, const float* __restrict__ b_ih,
    const float* __restrict__ w_hh, const float* __restrict__ b_hh,
    const float* __restrict__ w1, const float* __restrict__ b1,
    const float* __restrict__ w2, const float* __restrict__ b2,
    const float* __restrict__ g_ff, const float* __restrict__ be_ff,
    const float* __restrict__ g_sl, const float* __restrict__ be_sl,
    const float* __restrict__ g_in, const float* __restrict__ be_in,
    float* __restrict__ out, int last) {
    __shared__ __align__(16) float pool[POOL_FLOATS];
    __shared__ int s_fin;

    unsigned int* xs32 = (unsigned int*)pool;
    float* attn_s = pool + 8704;
    float* qh = pool + 10752;
    float* sqs = pool + 11264;
    float* csts = pool + 11272;
    float* s_red = pool + 11280;   // [8][16]

    int b = blockIdx.y, c = blockIdx.x, tid = threadIdx.x;

    for (int k = tid; k < S * D; k += TPB) qh[k] = g_qhat[b * S * D + k];
    if (tid < S) {
        sqs[tid] = g_sq[b * S + tid];
        csts[tid] = g_cst[b * S + tid];
    }

    u64t acc01 = 0ULL;   // phase2 accumulator: (d=dd2, d+1) for slot ip
    float Tl[S], dl[S];
#pragma unroll
    for (int i = 0; i < S; i++) { Tl[i] = 0.f; dl[i] = 0.f; }

    const float* xb = x + ((size_t)b * NTOK + (size_t)c * NC) * D;
    const int ip = tid >> 5;          // slot owned in phase 2
    const int lane32 = tid & 31;      // word index (covers dims 2*lane32, +1)

    for (int t = 0; t < NC / TILE; t++) {
        __syncthreads();
        const float4* src = (const float4*)(xb + t * TILE * D);
#pragma unroll
        for (int k = 0; k < 16; k++) {
            int idx = tid + k * TPB;
            float4 v = src[idx];
            int row = idx >> 4, c4 = idx & 15;
            unsigned int w0 = bfpack(v.x, v.y);
            unsigned int w1p = bfpack(v.z, v.w);
            *(uint2*)&xs32[row * XSW + c4 * 2] = make_uint2(w0, w1p);
        }
        __syncthreads();

        // ---- phase 1: thread owns token j = tid (256 tokens)
        u64t dslP[S];
#pragma unroll
        for (int i = 0; i < S; i++) dslP[i] = 0ULL;
        u64t sA = 0ULL, sB = 0ULL, qA = 0ULL, qB = 0ULL;
        const uint2* xr2 = (const uint2*)&xs32[tid * XSW];
        const ulonglong2* qh2 = (const ulonglong2*)qh;
#pragma unroll
        for (int d4 = 0; d4 < 16; d4++) {
            uint2 raw = xr2[d4];
            u64t p01 = bfpair(raw.x);
            u64t p23 = bfpair(raw.y);
            sA = f2_add(sA, p01);
            sB = f2_add(sB, p23);
            qA = f2_fma(p01, p01, qA);
            qB = f2_fma(p23, p23, qB);
#pragma unroll
            for (int i = 0; i < S; i++) {
                ulonglong2 qp = qh2[i * 16 + d4];
                dslP[i] = f2_fma(qp.x, p01, dslP[i]);
                dslP[i] = f2_fma(qp.y, p23, dslP[i]);
            }
        }
        float2 sfin = f2_unpack(f2_add(sA, sB));
        float2 qfin = f2_unpack(f2_add(qA, qB));
        float sum = sfin.x + sfin.y;
        float s2 = qfin.x + qfin.y;

        float m = sum * (1.f / 64.f);
        float var = s2 * (1.f / 64.f) - m * m;
        float r = rsqrtf(var + 1e-5f);
        float mx = -1e30f, dots[S];
#pragma unroll
        for (int i = 0; i < S; i++) {
            float2 dp = f2_unpack(dslP[i]);
            float dsl = dp.x + dp.y;
            dots[i] = r * (dsl - m * sqs[i]) + csts[i];
            mx = fmaxf(mx, dots[i]);
        }
        float es = 0.f, ex[S];
#pragma unroll
        for (int i = 0; i < S; i++) { ex[i] = __expf(dots[i] - mx); es += ex[i]; }
        float inv = 1.f / es;
        float rm = r * m;
#pragma unroll
        for (int i = 0; i < S; i++) {
            float ai = ex[i] * inv + 1e-8f;
            dl[i] += ai;
            Tl[i] += ai * rm;
            attn_s[i * TILE + tid] = ai * r;
        }
        __syncthreads();

        // ---- phase 2: thread owns slot ip, dims (2*lane32, 2*lane32+1)
        const float4* arow = (const float4*)(attn_s + ip * TILE);
#pragma unroll 8
        for (int j4 = 0; j4 < TILE / 4; j4++) {
            float4 a = arow[j4];
            const unsigned int* xc = &xs32[j4 * 4 * XSW + lane32];
            unsigned int u0 = xc[0], u1 = xc[XSW], u2 = xc[2 * XSW], u3 = xc[3 * XSW];
            acc01 = f2_fma(bfpair(u0), f2_splat(a.x), acc01);
            acc01 = f2_fma(bfpair(u1), f2_splat(a.y), acc01);
            acc01 = f2_fma(bfpair(u2), f2_splat(a.z), acc01);
            acc01 = f2_fma(bfpair(u3), f2_splat(a.w), acc01);
        }
    }

    // ---- write P, Td partials
    {
        float2 pr = f2_unpack(acc01);
        float* Pp = &g_P[(b * CHUNKS + c) * S * D];
        Pp[ip * D + lane32 * 2] = pr.x;
        Pp[ip * D + lane32 * 2 + 1] = pr.y;
    }
#pragma unroll
    for (int i = 0; i < S; i++) {
#pragma unroll
        for (int off = 16; off; off >>= 1) {
            Tl[i] += __shfl_xor_sync(0xffffffffu, Tl[i], off);
            dl[i] += __shfl_xor_sync(0xffffffffu, dl[i], off);
        }
    }
    {
        int w = tid >> 5, lane = tid & 31;
        if (lane == 0) {
#pragma unroll
            for (int i = 0; i < S; i++) { s_red[w * 16 + i] = Tl[i]; s_red[w * 16 + 8 + i] = dl[i]; }
        }
    }
    __syncthreads();
    if (tid < 16) {
        float s = 0.f;
#pragma unroll
        for (int w = 0; w < 8; w++) s += s_red[w * 16 + tid];
        g_Td[(b * CHUNKS + c) * 16 + tid] = s;
    }
    __syncthreads();   // order g_Td/g_P stores before the ticket

    // ---- last-block ticket
    if (tid == 0) {
        __threadfence();
        int old = atomicAdd(&g_cnt[b], 1);
        s_fin = (old == CHUNKS - 1) ? 1 : 0;
        if (s_fin) g_cnt[b] = 0;
    }
    __syncthreads();
    if (!s_fin) return;
    __threadfence();

    // ================= epilogue (finisher block only) =================
    float* e_prev = pool;
    float* e_num = pool + 512;
    float* e_upd = pool + 1024;
    float* e_new = pool + 1536;
    float* e_ff = pool + 2048;
    float* e_h1 = pool + 2560;
    float* e_gx = pool + 3584;
    float* e_gh = pool + 5120;
    float* e_pp = pool + 6656;
    float* e_Td = pool + 8704;

    // ---- A: T/den + prev + P reduce
    if (tid < 16) {
        float s = 0.f;
#pragma unroll
        for (int c2 = 0; c2 < CHUNKS; c2++) s += g_Td[(b * CHUNKS + c2) * 16 + tid];
        e_Td[tid] = s;
    }
    for (int k = tid; k < 512; k += TPB) {
        e_prev[k] = g_slots[b * 512 + k];
        float P = 0.f;
#pragma unroll
        for (int c2 = 0; c2 < CHUNKS; c2++) P += g_P[(b * CHUNKS + c2) * 512 + k];
        e_pp[k] = P;
    }
    __syncthreads();
    for (int k = tid; k < 512; k += TPB) {
        int i = k >> 6, d = k & 63;
        e_num[k] = g_in[d] * (e_pp[k] - e_Td[i]) + e_Td[8 + i] * be_in[d];
    }
    __syncthreads();

    // ---- B: upd = (num @ wv)/den + bv  (thread owns d; 2 slots; 64-deep)
    {
        int d = tid & 63, sg = tid >> 6;   // slots 2sg, 2sg+1
        float a0 = 0.f, a1 = 0.f;
#pragma unroll 8
        for (int e = 0; e < 64; e++) {
            float w = wv[e * 64 + d];
            a0 += e_num[(2 * sg) * 64 + e] * w;
            a1 += e_num[(2 * sg + 1) * 64 + e] * w;
        }
        e_upd[(2 * sg) * 64 + d] = a0 / e_Td[8 + 2 * sg] + bv[d];
        e_upd[(2 * sg + 1) * 64 + d] = a1 / e_Td[8 + 2 * sg + 1] + bv[d];
    }
    __syncthreads();

    // ---- C: GRU gates (threads 0..191 own o; 8 slot accs each)
    if (tid < 192) {
        int o = tid;
        float gx[8], gh[8];
#pragma unroll
        for (int i = 0; i < 8; i++) { gx[i] = 0.f; gh[i] = 0.f; }
#pragma unroll 4
        for (int e = 0; e < 64; e++) {
            float wi = w_ih[e * 192 + o];
            float wh = w_hh[e * 192 + o];
#pragma unroll
            for (int i = 0; i < 8; i++) {
                gx[i] += e_upd[i * 64 + e] * wi;
                gh[i] += e_prev[i * 64 + e] * wh;
            }
        }
        float bi = b_ih[o], bh = b_hh[o];
#pragma unroll
        for (int i = 0; i < 8; i++) {
            e_gx[i * 192 + o] = gx[i] + bi;
            e_gh[i * 192 + o] = gh[i] + bh;
        }
    }
    __syncthreads();
#pragma unroll
    for (int rep = 0; rep < 2; rep++) {
        int k = tid + rep * TPB;
        int i = k >> 6, d = k & 63, o = i * 192;
        float rx = e_gx[o + d] + e_gh[o + d];
        float zx = e_gx[o + 64 + d] + e_gh[o + 64 + d];
        float nx = e_gx[o + 128 + d];
        float nh = e_gh[o + 128 + d];
        float r = 1.f / (1.f + __expf(-rx));
        float z = 1.f / (1.f + __expf(-zx));
        float n = tanhf(nx + r * nh);
        e_new[k] = (1.f - z) * n + z * e_prev[k];
    }
    __syncthreads();

    // ---- D: ff = LN(new, g_ff)  (8 warps, one slot each)
    {
        int w = tid >> 5, lane = tid & 31;
        float v0 = e_new[w * 64 + lane], v1 = e_new[w * 64 + 32 + lane];
        float s = v0 + v1, s2 = v0 * v0 + v1 * v1;
#pragma unroll
        for (int off = 16; off; off >>= 1) {
            s += __shfl_xor_sync(0xffffffffu, s, off);
            s2 += __shfl_xor_sync(0xffffffffu, s2, off);
        }
        float m = s * (1.f / 64.f);
        float var = s2 * (1.f / 64.f) - m * m;
        float r = rsqrtf(var + 1e-5f);
        e_ff[w * 64 + lane] = (v0 - m) * r * g_ff[lane] + be_ff[lane];
        e_ff[w * 64 + 32 + lane] = (v1 - m) * r * g_ff[lane + 32] + be_ff[lane + 32];
    }
    __syncthreads();

    // ---- E: h1 = relu(ff @ w1 + b1)  (o=tid&127; half e-split; 8 slot accs)
    {
        int o = tid & 127, half = tid >> 7;
        float a[8];
        float binit = half ? 0.f : b1[o];
#pragma unroll
        for (int i = 0; i < 8; i++) a[i] = binit;
#pragma unroll 4
        for (int e = half * 32; e < half * 32 + 32; e++) {
            float w = w1[e * 128 + o];
#pragma unroll
            for (int i = 0; i < 8; i++) a[i] += e_ff[i * 64 + e] * w;
        }
#pragma unroll
        for (int i = 0; i < 8; i++) e_pp[half * 1024 + i * 128 + o] = a[i];
    }
    __syncthreads();
#pragma unroll
    for (int rep = 0; rep < 4; rep++) {
        int k = tid + rep * TPB;
        e_h1[k] = fmaxf(e_pp[k] + e_pp[1024 + k], 0.f);
    }
    __syncthreads();

    // ---- F: slots = new + h1 @ w2 + b2  (d=tid&63; 4-part e-split of 128; 8 accs)
    {
        int d = tid & 63, part = tid >> 6;
        float a[8];
#pragma unroll
        for (int i = 0; i < 8; i++) a[i] = 0.f;
#pragma unroll 4
        for (int e = part * 32; e < part * 32 + 32; e++) {
            float w = w2[e * 64 + d];
#pragma unroll
            for (int i = 0; i < 8; i++) a[i] += e_h1[i * 128 + e] * w;
        }
#pragma unroll
        for (int i = 0; i < 8; i++) e_pp[part * 512 + i * 64 + d] = a[i];
    }
    __syncthreads();
#pragma unroll
    for (int rep = 0; rep < 2; rep++) {
        int k = tid + rep * TPB;
        int d = k & 63;
        float val = e_new[k] + b2[d] + e_pp[k] + e_pp[512 + k] + e_pp[1024 + k] + e_pp[1536 + k];
        g_slots[b * 512 + k] = val;
        if (last) out[b * 512 + k] = val;
        e_new[k] = val;
    }
    if (last) return;
    __syncthreads();

    // ---- G: qfold
    {
        int w = tid >> 5, lane = tid & 31;
        float v0 = e_new[w * 64 + lane], v1 = e_new[w * 64 + 32 + lane];
        float s = v0 + v1, s2 = v0 * v0 + v1 * v1;
#pragma unroll
        for (int off = 16; off; off >>= 1) {
            s += __shfl_xor_sync(0xffffffffu, s, off);
            s2 += __shfl_xor_sync(0xffffffffu, s2, off);
        }
        float m = s * (1.f / 64.f);
        float var = s2 * (1.f / 64.f) - m * m;
        float r = rsqrtf(var + 1e-5f);
        e_ff[w * 64 + lane] = (v0 - m) * r * g_sl[lane] + be_sl[lane];
        e_ff[w * 64 + 32 + lane] = (v1 - m) * r * g_sl[lane + 32] + be_sl[lane + 32];
    }
    __syncthreads();
    {
        int d = tid & 63, part = tid >> 6;
        float a[8];
        float binit = part ? 0.f : g_bqk[d];
#pragma unroll
        for (int i = 0; i < 8; i++) a[i] = binit;
#pragma unroll 4
        for (int e = part * 16; e < part * 16 + 16; e++) {
            float w = g_wqk[e * 64 + d];
#pragma unroll
            for (int i = 0; i < 8; i++) a[i] += e_ff[i * 64 + e] * w;
        }
#pragma unroll
        for (int i = 0; i < 8; i++) e_pp[part * 512 + i * 64 + d] = a[i];
    }
    __syncthreads();
#pragma unroll
    for (int rep = 0; rep < 2; rep++) {
        int k = tid + rep * TPB;
        int d = k & 63;
        float qt = 0.125f * (e_pp[k] + e_pp[512 + k] + e_pp[1024 + k] + e_pp[1536 + k]);
        float qhv = qt * g_in[d];
        g_qhat[b * 512 + k] = qhv;
        e_gx[k] = qhv;
        e_gh[k] = qt * be_in[d];
    }
    __syncthreads();
    {
        int w = tid >> 5, lane = tid & 31;
        float sq = e_gx[w * 64 + lane] + e_gx[w * 64 + lane + 32];
        float cb = e_gh[w * 64 + lane] + e_gh[w * 64 + lane + 32];
        float qb = e_ff[w * 64 + lane] * g_wqbk[lane] + e_ff[w * 64 + lane + 32] * g_wqbk[lane + 32];
#pragma unroll
        for (int off = 16; off; off >>= 1) {
            sq += __shfl_xor_sync(0xffffffffu, sq, off);
            cb += __shfl_xor_sync(0xffffffffu, cb, off);
            qb += __shfl_xor_sync(0xffffffffu, qb, off);
        }
        if (lane == 0) {
            g_sq[b * S + w] = sq;
            g_cst[b * S + w] = cb + 0.125f * (qb + g_bqbk[0]);
        }
    }
}

// ---------------- launch ----------------
extern "C" void kernel_launch(void* const* d_in, const int* in_sizes, int n_in,
                              void* d_out, int out_size) {
    (void)in_sizes; (void)n_in; (void)out_size;
    const float* inputs = (const float*)d_in[0];
    const float* noise  = (const float*)d_in[1];
    const float* mu     = (const float*)d_in[2];
    const float* ls     = (const float*)d_in[3];
    const float* wq = (const float*)d_in[4];
    const float* bq = (const float*)d_in[5];
    const float* wk = (const float*)d_in[6];
    const float* bk = (const float*)d_in[7];
    const float* wv = (const float*)d_in[8];
    const float* bv = (const float*)d_in[9];
    const float* w_ih = (const float*)d_in[10];
    const float* b_ih = (const float*)d_in[11];
    const float* w_hh = (const float*)d_in[12];
    const float* b_hh = (const float*)d_in[13];
    const float* w1 = (const float*)d_in[14];
    const float* b1 = (const float*)d_in[15];
    const float* w2 = (const float*)d_in[16];
    const float* b2 = (const float*)d_in[17];
    const float* gin = (const float*)d_in[18];
    const float* bin = (const float*)d_in[19];
    const float* gsl = (const float*)d_in[20];
    const float* bsl = (const float*)d_in[21];
    const float* gff = (const float*)d_in[22];
    const float* bff = (const float*)d_in[23];
    float* out = (float*)d_out;

    k_pre<<<1, 256>>>(wq, bq, wk, bk);
    k_init<<<B, 256>>>(noise, mu, ls, gsl, bsl, gin, bin);
    for (int it = 0; it < 3; it++) {
        k_main<<<dim3(CHUNKS, B), TPB>>>(inputs,
                                         wv, bv, w_ih, b_ih, w_hh, b_hh,
                                         w1, b1, w2, b2,
                                         gff, bff, gsl, bsl, gin, bin,
                                         out, it == 2 ? 1 : 0);
    }
}